// round 12
// baseline (speedup 1.0000x reference)
#include <cuda_runtime.h>
#include <cuda_bf16.h>

#define N_NODES 100000
#define N_EDGES 600000
#define F 128
#define SCAN_B 512
#define NB_SCAN ((N_NODES + SCAN_B - 1) / SCAN_B)   // 196

// ---------------- scratch (device globals: proven-safe set) -------------------
__device__ int   g_deg[N_NODES];
__device__ int   g_cur[N_NODES];
__device__ int   g_off[N_NODES + 1];
__device__ int   g_srcs[N_EDGES];
__device__ int   g_bsum[256];
__device__ float g_agg[(size_t)N_NODES * F];
__device__ float g_h1 [(size_t)N_NODES * F];

// ---------------- CSR build ---------------------------------------------------
__global__ void zero_kernel() {
    int i = blockIdx.x * blockDim.x + threadIdx.x;
    if (i < N_NODES) { g_deg[i] = 0; g_cur[i] = 0; }
}

__global__ void hist_kernel(const int* __restrict__ edges) {
    int i = blockIdx.x * blockDim.x + threadIdx.x;
    if (i < N_EDGES) {
        unsigned d = (unsigned)edges[N_EDGES + i];
        if (d < N_NODES) atomicAdd(&g_deg[d], 1);
    }
}

__global__ void scan1_kernel() {
    __shared__ int s[SCAN_B];
    int i = blockIdx.x * SCAN_B + threadIdx.x;
    int v = (i < N_NODES) ? g_deg[i] : 0;
    s[threadIdx.x] = v;
    __syncthreads();
    for (int off = 1; off < SCAN_B; off <<= 1) {
        int t = (threadIdx.x >= off) ? s[threadIdx.x - off] : 0;
        __syncthreads();
        s[threadIdx.x] += t;
        __syncthreads();
    }
    if (i < N_NODES) g_off[i] = s[threadIdx.x] - v;
    if (threadIdx.x == SCAN_B - 1) g_bsum[blockIdx.x] = s[SCAN_B - 1];
}

__global__ void scan2_kernel() {
    __shared__ int s[256];
    int t = threadIdx.x;
    int v = (t < NB_SCAN) ? g_bsum[t] : 0;
    s[t] = v;
    __syncthreads();
    for (int off = 1; off < 256; off <<= 1) {
        int u = (t >= off) ? s[t - off] : 0;
        __syncthreads();
        s[t] += u;
        __syncthreads();
    }
    if (t < NB_SCAN) g_bsum[t] = s[t] - v;
    if (t == 255) g_off[N_NODES] = s[255];
}

__global__ void scan3_kernel() {
    int i = blockIdx.x * SCAN_B + threadIdx.x;
    if (i < N_NODES) g_off[i] += g_bsum[blockIdx.x];
}

__global__ void fill_kernel(const int* __restrict__ edges) {
    int i = blockIdx.x * blockDim.x + threadIdx.x;
    if (i < N_EDGES) {
        unsigned s = (unsigned)edges[i];
        unsigned d = (unsigned)edges[N_EDGES + i];
        if (s < N_NODES && d < N_NODES) {
            int p = atomicAdd(&g_cur[d], 1);
            g_srcs[g_off[d] + p] = (int)s;
        }
    }
}

// ---------------- mean aggregation: one warp per node, 4-way MLP unroll -------
template <int SRC_SEL>
__global__ void agg_kernel(const float* __restrict__ in) {
    int w = (blockIdx.x * blockDim.x + threadIdx.x) >> 5;
    if (w >= N_NODES) return;
    int lane = threadIdx.x & 31;
    int beg = g_off[w], end = g_off[w + 1];
    const float* src = (SRC_SEL == 0) ? in : (const float*)g_h1;
    const float4* in4 = reinterpret_cast<const float4*>(src);
    float x0 = 0.f, x1 = 0.f, x2 = 0.f, x3 = 0.f;
    int e = beg;
    for (; e + 4 <= end; e += 4) {
        int s0 = g_srcs[e], s1 = g_srcs[e + 1], s2 = g_srcs[e + 2], s3 = g_srcs[e + 3];
        float4 v0 = in4[(size_t)s0 * 32 + lane];
        float4 v1 = in4[(size_t)s1 * 32 + lane];
        float4 v2 = in4[(size_t)s2 * 32 + lane];
        float4 v3 = in4[(size_t)s3 * 32 + lane];
        x0 += v0.x + v1.x + v2.x + v3.x;
        x1 += v0.y + v1.y + v2.y + v3.y;
        x2 += v0.z + v1.z + v2.z + v3.z;
        x3 += v0.w + v1.w + v2.w + v3.w;
    }
    for (; e < end; e++) {
        int s = g_srcs[e];
        float4 v = in4[(size_t)s * 32 + lane];
        x0 += v.x; x1 += v.y; x2 += v.z; x3 += v.w;
    }
    int d = end - beg;
    float inv = (d > 0) ? (1.0f / (float)d) : 0.0f;
    float4 r; r.x = x0 * inv; r.y = x1 * inv; r.z = x2 * inv; r.w = x3 * inv;
    reinterpret_cast<float4*>(g_agg)[(size_t)w * 32 + lane] = r;
}

// ---------------- mma.sync bf16-split GEMM, 128-row block tile ----------------
// Per block: out[128m x 128n] = sum_pass A_pass@W_pass^T (+bias, opt relu).
// smem: Ah[0,10240) Al[10240,20480) Wh[20480,30720) Wl[30720,40960); stride 80B.
#define MMAS(c0, c1, c2, c3, a0, a1, a2, a3, b0, b1) \
    asm volatile("mma.sync.aligned.m16n8k16.row.col.f32.bf16.bf16.f32 " \
        "{%0,%1,%2,%3}, {%4,%5,%6,%7}, {%8,%9}, {%0,%1,%2,%3};" \
        : "+f"(c0), "+f"(c1), "+f"(c2), "+f"(c3) \
        : "r"(a0), "r"(a1), "r"(a2), "r"(a3), "r"(b0), "r"(b1))

#define DACC(mt, nt) \
    float C##mt##nt##_0 = 0.f, C##mt##nt##_1 = 0.f, C##mt##nt##_2 = 0.f, C##mt##nt##_3 = 0.f

// W fragments: loaded once per k-slice (16 regs live).
#define LDW(nt) \
    unsigned WH##nt##_0, WH##nt##_1, WL##nt##_0, WL##nt##_1; \
    { unsigned o_ = wBase + (unsigned)(nt * 8 * 80) + kb; \
      WH##nt##_0 = *reinterpret_cast<const unsigned*>(sm + o_); \
      WH##nt##_1 = *reinterpret_cast<const unsigned*>(sm + o_ + 16); \
      WL##nt##_0 = *reinterpret_cast<const unsigned*>(sm + o_ + 10240); \
      WL##nt##_1 = *reinterpret_cast<const unsigned*>(sm + o_ + 10256); }

// Per-mt block: load 8 A frags, fire 12 MMAs, frags die at block end.
#define MT_BLOCK(mt) { \
    unsigned AH0_, AH1_, AH2_, AH3_, AL0_, AL1_, AL2_, AL3_; \
    unsigned o_ = aBase + (unsigned)(mt * 16 * 80) + kb; \
    AH0_ = *reinterpret_cast<const unsigned*>(sm + o_); \
    AH1_ = *reinterpret_cast<const unsigned*>(sm + o_ + 640); \
    AH2_ = *reinterpret_cast<const unsigned*>(sm + o_ + 16); \
    AH3_ = *reinterpret_cast<const unsigned*>(sm + o_ + 656); \
    AL0_ = *reinterpret_cast<const unsigned*>(sm + o_ + 10240); \
    AL1_ = *reinterpret_cast<const unsigned*>(sm + o_ + 10880); \
    AL2_ = *reinterpret_cast<const unsigned*>(sm + o_ + 10256); \
    AL3_ = *reinterpret_cast<const unsigned*>(sm + o_ + 10896); \
    MMAS(C##mt##0_0, C##mt##0_1, C##mt##0_2, C##mt##0_3, AH0_, AH1_, AH2_, AH3_, WH0_0, WH0_1); \
    MMAS(C##mt##0_0, C##mt##0_1, C##mt##0_2, C##mt##0_3, AH0_, AH1_, AH2_, AH3_, WL0_0, WL0_1); \
    MMAS(C##mt##0_0, C##mt##0_1, C##mt##0_2, C##mt##0_3, AL0_, AL1_, AL2_, AL3_, WH0_0, WH0_1); \
    MMAS(C##mt##1_0, C##mt##1_1, C##mt##1_2, C##mt##1_3, AH0_, AH1_, AH2_, AH3_, WH1_0, WH1_1); \
    MMAS(C##mt##1_0, C##mt##1_1, C##mt##1_2, C##mt##1_3, AH0_, AH1_, AH2_, AH3_, WL1_0, WL1_1); \
    MMAS(C##mt##1_0, C##mt##1_1, C##mt##1_2, C##mt##1_3, AL0_, AL1_, AL2_, AL3_, WH1_0, WH1_1); \
    MMAS(C##mt##2_0, C##mt##2_1, C##mt##2_2, C##mt##2_3, AH0_, AH1_, AH2_, AH3_, WH2_0, WH2_1); \
    MMAS(C##mt##2_0, C##mt##2_1, C##mt##2_2, C##mt##2_3, AH0_, AH1_, AH2_, AH3_, WL2_0, WL2_1); \
    MMAS(C##mt##2_0, C##mt##2_1, C##mt##2_2, C##mt##2_3, AL0_, AL1_, AL2_, AL3_, WH2_0, WH2_1); \
    MMAS(C##mt##3_0, C##mt##3_1, C##mt##3_2, C##mt##3_3, AH0_, AH1_, AH2_, AH3_, WH3_0, WH3_1); \
    MMAS(C##mt##3_0, C##mt##3_1, C##mt##3_2, C##mt##3_3, AH0_, AH1_, AH2_, AH3_, WL3_0, WL3_1); \
    MMAS(C##mt##3_0, C##mt##3_1, C##mt##3_2, C##mt##3_3, AL0_, AL1_, AL2_, AL3_, WH3_0, WH3_1); }

#define DEC_KS(kb_) { \
    unsigned kb = (kb_); \
    LDW(0) LDW(1) LDW(2) LDW(3) \
    MT_BLOCK(0) MT_BLOCK(1) MT_BLOCK(2) MT_BLOCK(3) }

#define DEPI(mt, nt) { \
    int nc = wn * 32 + nt * 8 + 2 * r4; \
    int m = m0 + wm * 64 + mt * 16 + q4; \
    float v0 = C##mt##nt##_0 + bias[nc], v1 = C##mt##nt##_1 + bias[nc + 1]; \
    float v2 = C##mt##nt##_2 + bias[nc], v3 = C##mt##nt##_3 + bias[nc + 1]; \
    if (RELU) { v0 = fmaxf(v0, 0.f); v1 = fmaxf(v1, 0.f); \
                v2 = fmaxf(v2, 0.f); v3 = fmaxf(v3, 0.f); } \
    if (m < n) *reinterpret_cast<float2*>(&out[(size_t)m * F + nc]) = make_float2(v0, v1); \
    if (m + 8 < n) *reinterpret_cast<float2*>(&out[(size_t)(m + 8) * F + nc]) = make_float2(v2, v3); }

#define SPLITPACK(vx, vy, hp_, lp_) { \
    __nv_bfloat16 h0_ = __float2bfloat16_rn(vx); \
    __nv_bfloat16 h1_ = __float2bfloat16_rn(vy); \
    __nv_bfloat16 l0_ = __float2bfloat16_rn((vx) - __bfloat162float(h0_)); \
    __nv_bfloat16 l1_ = __float2bfloat16_rn((vy) - __bfloat162float(h1_)); \
    hp_ = (unsigned)__bfloat16_as_ushort(h0_) | ((unsigned)__bfloat16_as_ushort(h1_) << 16); \
    lp_ = (unsigned)__bfloat16_as_ushort(l0_) | ((unsigned)__bfloat16_as_ushort(l1_) << 16); }

// CFG 1: out(g_h1) = relu(g_agg@w1^T + b + x(param a2)@w2^T)   [NPASS=2]
// CFG 2: out(param) = g_agg@w1^T + b + g_h1@w2^T               [NPASS=2]
// CFG 3: out(param) = a2(param)@w1^T + b                       [NPASS=1]
template <int CFG>
__global__ void __launch_bounds__(256)
layer_mma(const float* __restrict__ a2p, const float* __restrict__ w1p,
          const float* __restrict__ w2p, const float* __restrict__ bias,
          float* __restrict__ outp, int n) {
    __shared__ __align__(16) char sm[40960];

    const bool RELU = (CFG == 1);
    const int NPASS = (CFG == 3) ? 1 : 2;
    float* out = (CFG == 1) ? (float*)g_h1 : outp;

    int tid = threadIdx.x, lane = tid & 31, wid = tid >> 5;
    int wm = wid & 1, wn = wid >> 1;           // 2 m-warps (64 rows each) x 4 n-warps
    int q4 = lane >> 2, r4 = lane & 3;
    int m0 = blockIdx.x * 128;

    DACC(0, 0); DACC(0, 1); DACC(0, 2); DACC(0, 3);
    DACC(1, 0); DACC(1, 1); DACC(1, 2); DACC(1, 3);
    DACC(2, 0); DACC(2, 1); DACC(2, 2); DACC(2, 3);
    DACC(3, 0); DACC(3, 1); DACC(3, 2); DACC(3, 3);

    unsigned aBase = (unsigned)((wm * 64 + q4) * 80 + r4 * 4);
    unsigned wBase = (unsigned)(20480 + (wn * 32 + q4) * 80 + r4 * 4);

    for (int p = 0; p < NPASS; p++) {
        const float* ap;
        if (CFG == 3)      ap = a2p;
        else if (p == 0)   ap = (const float*)g_agg;
        else if (CFG == 1) ap = a2p;
        else               ap = (const float*)g_h1;
        const float* wp = (p == 0) ? w1p : w2p;
        const float4* a4 = reinterpret_cast<const float4*>(ap);
        const float4* w4 = reinterpret_cast<const float4*>(wp);

        for (int ck = 0; ck < 4; ck++) {
            __syncthreads();
            // A: 128 rows x 32 k fp32 -> split planes. 4 float4/thread.
#pragma unroll
            for (int i = 0; i < 4; i++) {
                int f = tid + i * 256;               // 0..1023
                int row = f >> 3, j = f & 7;
                float4 v = make_float4(0.f, 0.f, 0.f, 0.f);
                if (m0 + row < n) v = a4[(size_t)(m0 + row) * 32 + ck * 8 + j];
                unsigned hp0, lp0, hp1, lp1;
                SPLITPACK(v.x, v.y, hp0, lp0);
                SPLITPACK(v.z, v.w, hp1, lp1);
                *reinterpret_cast<uint2*>(sm + row * 80 + j * 8) = make_uint2(hp0, hp1);
                *reinterpret_cast<uint2*>(sm + 10240 + row * 80 + j * 8) = make_uint2(lp0, lp1);
            }
            // W: 128 rows x 32 k fp32 -> split planes. 4 float4/thread.
#pragma unroll
            for (int i = 0; i < 4; i++) {
                int f = tid + i * 256;               // 0..1023
                int row = f >> 3, j = f & 7;
                float4 v = w4[(size_t)row * 32 + ck * 8 + j];
                unsigned hp0, lp0, hp1, lp1;
                SPLITPACK(v.x, v.y, hp0, lp0);
                SPLITPACK(v.z, v.w, hp1, lp1);
                *reinterpret_cast<uint2*>(sm + 20480 + row * 80 + j * 8) = make_uint2(hp0, hp1);
                *reinterpret_cast<uint2*>(sm + 30720 + row * 80 + j * 8) = make_uint2(lp0, lp1);
            }
            __syncthreads();
            DEC_KS(0u)
            DEC_KS(32u)
        }
    }

    DEPI(0, 0) DEPI(0, 1) DEPI(0, 2) DEPI(0, 3)
    DEPI(1, 0) DEPI(1, 1) DEPI(1, 2) DEPI(1, 3)
    DEPI(2, 0) DEPI(2, 1) DEPI(2, 2) DEPI(2, 3)
    DEPI(3, 0) DEPI(3, 1) DEPI(3, 2) DEPI(3, 3)
}

// ---------------- launch ------------------------------------------------------
extern "C" void kernel_launch(void* const* d_in, const int* in_sizes, int n_in,
                              void* d_out, int out_size) {
    const float* x     = (const float*)d_in[0];
    const int*   xedge = (const int*)d_in[1];      // int32 [2, E]
    const float* w1l   = (const float*)d_in[2];
    const float* b1l   = (const float*)d_in[3];
    const float* w1r   = (const float*)d_in[4];
    const float* w2l   = (const float*)d_in[5];
    const float* b2l   = (const float*)d_in[6];
    const float* w2r   = (const float*)d_in[7];
    const float* wdec  = (const float*)d_in[8];
    const float* bdec  = (const float*)d_in[9];

    float* out_h  = (float*)d_out;
    float* out_dx = out_h + (size_t)N_NODES * F;

    const int agg_blocks = (N_NODES + 7) / 8;          // 12500
    const int mma_blocks = (N_NODES + 127) / 128;      // 782

    // CSR build
    zero_kernel<<<(N_NODES + 255) / 256, 256>>>();
    hist_kernel<<<(N_EDGES + 255) / 256, 256>>>(xedge);
    scan1_kernel<<<NB_SCAN, SCAN_B>>>();
    scan2_kernel<<<1, 256>>>();
    scan3_kernel<<<NB_SCAN, SCAN_B>>>();
    fill_kernel<<<(N_EDGES + 255) / 256, 256>>>(xedge);

    // Layer 1: agg(x) -> g_agg; g_h1 = relu(g_agg@w1l^T + b1l + x@w1r^T)
    agg_kernel<0><<<agg_blocks, 256>>>(x);
    layer_mma<1><<<mma_blocks, 256>>>(x, w1l, w1r, b1l, nullptr, N_NODES);

    // Layer 2: agg(g_h1) -> g_agg; out_h = g_agg@w2l^T + b2l + g_h1@w2r^T
    agg_kernel<1><<<agg_blocks, 256>>>(nullptr);
    layer_mma<2><<<mma_blocks, 256>>>(nullptr, w2l, w2r, b2l, out_h, N_NODES);

    // Decoder: out_dx = out_h@wdec^T + bdec
    layer_mma<3><<<mma_blocks, 256>>>(out_h, wdec, nullptr, bdec, out_dx, N_NODES);
}

// round 13
// speedup vs baseline: 1.2160x; 1.2160x over previous
#include <cuda_runtime.h>
#include <cuda_bf16.h>

#define N_NODES 100000
#define N_EDGES 600000
#define F 128
#define SCAN_B 512
#define NB_SCAN ((N_NODES + SCAN_B - 1) / SCAN_B)   // 196

// ---------------- scratch (device globals: proven-safe set) -------------------
__device__ int   g_deg[N_NODES];
__device__ int   g_cur[N_NODES];
__device__ int   g_off[N_NODES + 1];
__device__ int   g_srcs[N_EDGES];
__device__ int   g_bsum[256];
__device__ float g_agg[(size_t)N_NODES * F];
__device__ float g_h1 [(size_t)N_NODES * F];

// ---------------- CSR build ---------------------------------------------------
__global__ void zero_kernel() {
    int i = blockIdx.x * blockDim.x + threadIdx.x;
    if (i < N_NODES) g_deg[i] = 0;
}

__global__ void hist_kernel(const int* __restrict__ edges) {
    int i = blockIdx.x * blockDim.x + threadIdx.x;
    if (i < N_EDGES) {
        unsigned d = (unsigned)edges[N_EDGES + i];
        if (d < N_NODES) atomicAdd(&g_deg[d], 1);
    }
}

__global__ void scan1_kernel() {
    __shared__ int s[SCAN_B];
    int i = blockIdx.x * SCAN_B + threadIdx.x;
    int v = (i < N_NODES) ? g_deg[i] : 0;
    s[threadIdx.x] = v;
    __syncthreads();
    for (int off = 1; off < SCAN_B; off <<= 1) {
        int t = (threadIdx.x >= off) ? s[threadIdx.x - off] : 0;
        __syncthreads();
        s[threadIdx.x] += t;
        __syncthreads();
    }
    if (i < N_NODES) g_off[i] = s[threadIdx.x] - v;
    if (threadIdx.x == SCAN_B - 1) g_bsum[blockIdx.x] = s[SCAN_B - 1];
}

__global__ void scan2_kernel() {
    __shared__ int s[256];
    int t = threadIdx.x;
    int v = (t < NB_SCAN) ? g_bsum[t] : 0;
    s[t] = v;
    __syncthreads();
    for (int off = 1; off < 256; off <<= 1) {
        int u = (t >= off) ? s[t - off] : 0;
        __syncthreads();
        s[t] += u;
        __syncthreads();
    }
    if (t < NB_SCAN) g_bsum[t] = s[t] - v;
    if (t == 255) g_off[N_NODES] = s[255];
}

__global__ void scan3_kernel() {
    int i = blockIdx.x * SCAN_B + threadIdx.x;
    if (i < N_NODES) {
        int o = g_off[i] + g_bsum[blockIdx.x];
        g_off[i] = o;
        g_cur[i] = o;          // absolute write cursor for fill
    }
}

__global__ void fill_kernel(const int* __restrict__ edges) {
    int i = blockIdx.x * blockDim.x + threadIdx.x;
    if (i < N_EDGES) {
        unsigned s = (unsigned)edges[i];
        unsigned d = (unsigned)edges[N_EDGES + i];
        if (s < N_NODES && d < N_NODES) {
            int p = atomicAdd(&g_cur[d], 1);
            g_srcs[p] = (int)s;
        }
    }
}

// ---------------- mean aggregation: one warp per node, 4-way MLP unroll -------
template <int SRC_SEL>
__global__ void agg_kernel(const float* __restrict__ in) {
    int w = (blockIdx.x * blockDim.x + threadIdx.x) >> 5;
    if (w >= N_NODES) return;
    int lane = threadIdx.x & 31;
    int beg = g_off[w], end = g_off[w + 1];
    const float* src = (SRC_SEL == 0) ? in : (const float*)g_h1;
    const float4* in4 = reinterpret_cast<const float4*>(src);
    float x0 = 0.f, x1 = 0.f, x2 = 0.f, x3 = 0.f;
    int e = beg;
    for (; e + 4 <= end; e += 4) {
        int s0 = g_srcs[e], s1 = g_srcs[e + 1], s2 = g_srcs[e + 2], s3 = g_srcs[e + 3];
        float4 v0 = in4[(size_t)s0 * 32 + lane];
        float4 v1 = in4[(size_t)s1 * 32 + lane];
        float4 v2 = in4[(size_t)s2 * 32 + lane];
        float4 v3 = in4[(size_t)s3 * 32 + lane];
        x0 += v0.x + v1.x + v2.x + v3.x;
        x1 += v0.y + v1.y + v2.y + v3.y;
        x2 += v0.z + v1.z + v2.z + v3.z;
        x3 += v0.w + v1.w + v2.w + v3.w;
    }
    for (; e < end; e++) {
        int s = g_srcs[e];
        float4 v = in4[(size_t)s * 32 + lane];
        x0 += v.x; x1 += v.y; x2 += v.z; x3 += v.w;
    }
    int d = end - beg;
    float inv = (d > 0) ? (1.0f / (float)d) : 0.0f;
    float4 r; r.x = x0 * inv; r.y = x1 * inv; r.z = x2 * inv; r.w = x3 * inv;
    reinterpret_cast<float4*>(g_agg)[(size_t)w * 32 + lane] = r;
}

// ---------------- mma.sync bf16-split GEMM (64-row tile + reg prefetch) -------
// Per block: out[64m x 128n] = sum_pass A_pass@W_pass^T (+bias, opt relu).
// smem: Ah[0,5120) Al[5120,10240) Wh[10240,20480) Wl[20480,30720); stride 80B.
#define MMAS(c0, c1, c2, c3, a0, a1, a2, a3, b0, b1) \
    asm volatile("mma.sync.aligned.m16n8k16.row.col.f32.bf16.bf16.f32 " \
        "{%0,%1,%2,%3}, {%4,%5,%6,%7}, {%8,%9}, {%0,%1,%2,%3};" \
        : "+f"(c0), "+f"(c1), "+f"(c2), "+f"(c3) \
        : "r"(a0), "r"(a1), "r"(a2), "r"(a3), "r"(b0), "r"(b1))

#define DACC(mt, nt) \
    float C##mt##nt##_0 = 0.f, C##mt##nt##_1 = 0.f, C##mt##nt##_2 = 0.f, C##mt##nt##_3 = 0.f

#define LDA(mt) \
    unsigned AH##mt##_0, AH##mt##_1, AH##mt##_2, AH##mt##_3; \
    unsigned AL##mt##_0, AL##mt##_1, AL##mt##_2, AL##mt##_3; \
    { unsigned o_ = aBase + (unsigned)(mt * 16 * 80) + kb; \
      AH##mt##_0 = *reinterpret_cast<const unsigned*>(sm + o_); \
      AH##mt##_1 = *reinterpret_cast<const unsigned*>(sm + o_ + 640); \
      AH##mt##_2 = *reinterpret_cast<const unsigned*>(sm + o_ + 16); \
      AH##mt##_3 = *reinterpret_cast<const unsigned*>(sm + o_ + 656); \
      AL##mt##_0 = *reinterpret_cast<const unsigned*>(sm + o_ + 5120); \
      AL##mt##_1 = *reinterpret_cast<const unsigned*>(sm + o_ + 5760); \
      AL##mt##_2 = *reinterpret_cast<const unsigned*>(sm + o_ + 5136); \
      AL##mt##_3 = *reinterpret_cast<const unsigned*>(sm + o_ + 5776); }

#define LDW(nt) \
    unsigned WH##nt##_0, WH##nt##_1, WL##nt##_0, WL##nt##_1; \
    { unsigned o_ = wBase + (unsigned)(nt * 8 * 80) + kb; \
      WH##nt##_0 = *reinterpret_cast<const unsigned*>(sm + o_); \
      WH##nt##_1 = *reinterpret_cast<const unsigned*>(sm + o_ + 16); \
      WL##nt##_0 = *reinterpret_cast<const unsigned*>(sm + o_ + 10240); \
      WL##nt##_1 = *reinterpret_cast<const unsigned*>(sm + o_ + 10256); }

#define DOMMA(mt, nt) \
    MMAS(C##mt##nt##_0, C##mt##nt##_1, C##mt##nt##_2, C##mt##nt##_3, \
         AH##mt##_0, AH##mt##_1, AH##mt##_2, AH##mt##_3, WH##nt##_0, WH##nt##_1); \
    MMAS(C##mt##nt##_0, C##mt##nt##_1, C##mt##nt##_2, C##mt##nt##_3, \
         AH##mt##_0, AH##mt##_1, AH##mt##_2, AH##mt##_3, WL##nt##_0, WL##nt##_1); \
    MMAS(C##mt##nt##_0, C##mt##nt##_1, C##mt##nt##_2, C##mt##nt##_3, \
         AL##mt##_0, AL##mt##_1, AL##mt##_2, AL##mt##_3, WH##nt##_0, WH##nt##_1)

#define DEC_KS(kb_) { \
    unsigned kb = (kb_); \
    LDA(0) LDA(1) LDW(0) LDW(1) LDW(2) LDW(3) \
    DOMMA(0, 0); DOMMA(0, 1); DOMMA(0, 2); DOMMA(0, 3); \
    DOMMA(1, 0); DOMMA(1, 1); DOMMA(1, 2); DOMMA(1, 3); }

#define DEPI(mt, nt) { \
    int nc = wn * 32 + nt * 8 + 2 * r4; \
    int m = m0 + wm * 32 + mt * 16 + q4; \
    float v0 = C##mt##nt##_0 + bias[nc], v1 = C##mt##nt##_1 + bias[nc + 1]; \
    float v2 = C##mt##nt##_2 + bias[nc], v3 = C##mt##nt##_3 + bias[nc + 1]; \
    if (RELU) { v0 = fmaxf(v0, 0.f); v1 = fmaxf(v1, 0.f); \
                v2 = fmaxf(v2, 0.f); v3 = fmaxf(v3, 0.f); } \
    if (m < n) *reinterpret_cast<float2*>(&out[(size_t)m * F + nc]) = make_float2(v0, v1); \
    if (m + 8 < n) *reinterpret_cast<float2*>(&out[(size_t)(m + 8) * F + nc]) = make_float2(v2, v3); }

#define SPLITPACK(vx, vy, hp_, lp_) { \
    __nv_bfloat16 h0_ = __float2bfloat16_rn(vx); \
    __nv_bfloat16 h1_ = __float2bfloat16_rn(vy); \
    __nv_bfloat16 l0_ = __float2bfloat16_rn((vx) - __bfloat162float(h0_)); \
    __nv_bfloat16 l1_ = __float2bfloat16_rn((vy) - __bfloat162float(h1_)); \
    hp_ = (unsigned)__bfloat16_as_ushort(h0_) | ((unsigned)__bfloat16_as_ushort(h1_) << 16); \
    lp_ = (unsigned)__bfloat16_as_ushort(l0_) | ((unsigned)__bfloat16_as_ushort(l1_) << 16); }

// Store one prefetched float4 as split planes at (row, j) with plane base pb.
#define STORE_SPLIT4(pb, row, j, V) { \
    unsigned hp0_, lp0_, hp1_, lp1_; \
    SPLITPACK((V).x, (V).y, hp0_, lp0_); \
    SPLITPACK((V).z, (V).w, hp1_, lp1_); \
    *reinterpret_cast<uint2*>(sm + (pb) + (row) * 80 + (j) * 8) = make_uint2(hp0_, hp1_); \
    *reinterpret_cast<uint2*>(sm + (pb) + 5120 * ((pb) >= 10240 ? 2 : 1) + (row) * 80 + (j) * 8) = \
        make_uint2(lp0_, lp1_); }

// CFG 1: out(g_h1) = relu(g_agg@w1^T + b + x(param a2)@w2^T)   [NPASS=2]
// CFG 2: out(param) = g_agg@w1^T + b + g_h1@w2^T               [NPASS=2]
// CFG 3: out(param) = a2(param)@w1^T + b                       [NPASS=1]
template <int CFG>
__global__ void __launch_bounds__(256)
layer_mma(const float* __restrict__ a2p, const float* __restrict__ w1p,
          const float* __restrict__ w2p, const float* __restrict__ bias,
          float* __restrict__ outp, int n) {
    __shared__ __align__(16) char sm[30720];

    const bool RELU = (CFG == 1);
    const int NPASS = (CFG == 3) ? 1 : 2;
    const int NCHUNK = NPASS * 4;
    float* out = (CFG == 1) ? (float*)g_h1 : outp;

    int tid = threadIdx.x, lane = tid & 31, wid = tid >> 5;
    int wm = wid & 1, wn = wid >> 1;           // 2 m-warps x 4 n-warps
    int q4 = lane >> 2, r4 = lane & 3;
    int m0 = blockIdx.x * 64;

    DACC(0, 0); DACC(0, 1); DACC(0, 2); DACC(0, 3);
    DACC(1, 0); DACC(1, 1); DACC(1, 2); DACC(1, 3);

    unsigned aBase = (unsigned)((wm * 32 + q4) * 80 + r4 * 4);
    unsigned wBase = (unsigned)(10240 + (wn * 32 + q4) * 80 + r4 * 4);

    // loader coordinates (fixed per thread)
    int fA0 = tid * 2, fA1 = tid * 2 + 1;
    int rA0 = fA0 >> 3, jA0 = fA0 & 7;
    int rA1 = fA1 >> 3, jA1 = fA1 & 7;
    int rW0 = tid >> 3,          jW = tid & 7;   // W rows: tid>>3 + 32*i
    // prefetch registers
    float4 PA0, PA1, PW0, PW1, PW2, PW3;

    // PRELOAD(cc): fill PA*/PW* for chunk cc
#define PRELOAD(cc_) { \
        int p_ = (cc_) >> 2, ck_ = (cc_) & 3; \
        const float* ap_; \
        if (CFG == 3)      ap_ = a2p; \
        else if (p_ == 0)  ap_ = (const float*)g_agg; \
        else if (CFG == 1) ap_ = a2p; \
        else               ap_ = (const float*)g_h1; \
        const float* wp_ = (p_ == 0) ? w1p : w2p; \
        const float4* a4_ = reinterpret_cast<const float4*>(ap_); \
        const float4* w4_ = reinterpret_cast<const float4*>(wp_); \
        PA0 = (m0 + rA0 < n) ? a4_[(size_t)(m0 + rA0) * 32 + ck_ * 8 + jA0] \
                             : make_float4(0.f, 0.f, 0.f, 0.f); \
        PA1 = (m0 + rA1 < n) ? a4_[(size_t)(m0 + rA1) * 32 + ck_ * 8 + jA1] \
                             : make_float4(0.f, 0.f, 0.f, 0.f); \
        PW0 = w4_[(size_t)(rW0      ) * 32 + ck_ * 8 + jW]; \
        PW1 = w4_[(size_t)(rW0 +  32) * 32 + ck_ * 8 + jW]; \
        PW2 = w4_[(size_t)(rW0 +  64) * 32 + ck_ * 8 + jW]; \
        PW3 = w4_[(size_t)(rW0 +  96) * 32 + ck_ * 8 + jW]; }

    PRELOAD(0)
    for (int cc = 0; cc < NCHUNK; cc++) {
        __syncthreads();                       // smem free (prev compute done)
        // store current prefetched chunk as split planes
        {
            unsigned hp0, lp0, hp1, lp1;
            SPLITPACK(PA0.x, PA0.y, hp0, lp0); SPLITPACK(PA0.z, PA0.w, hp1, lp1);
            *reinterpret_cast<uint2*>(sm + rA0 * 80 + jA0 * 8) = make_uint2(hp0, hp1);
            *reinterpret_cast<uint2*>(sm + 5120 + rA0 * 80 + jA0 * 8) = make_uint2(lp0, lp1);
            SPLITPACK(PA1.x, PA1.y, hp0, lp0); SPLITPACK(PA1.z, PA1.w, hp1, lp1);
            *reinterpret_cast<uint2*>(sm + rA1 * 80 + jA1 * 8) = make_uint2(hp0, hp1);
            *reinterpret_cast<uint2*>(sm + 5120 + rA1 * 80 + jA1 * 8) = make_uint2(lp0, lp1);
            SPLITPACK(PW0.x, PW0.y, hp0, lp0); SPLITPACK(PW0.z, PW0.w, hp1, lp1);
            *reinterpret_cast<uint2*>(sm + 10240 + rW0 * 80 + jW * 8) = make_uint2(hp0, hp1);
            *reinterpret_cast<uint2*>(sm + 20480 + rW0 * 80 + jW * 8) = make_uint2(lp0, lp1);
            SPLITPACK(PW1.x, PW1.y, hp0, lp0); SPLITPACK(PW1.z, PW1.w, hp1, lp1);
            *reinterpret_cast<uint2*>(sm + 10240 + (rW0 + 32) * 80 + jW * 8) = make_uint2(hp0, hp1);
            *reinterpret_cast<uint2*>(sm + 20480 + (rW0 + 32) * 80 + jW * 8) = make_uint2(lp0, lp1);
            SPLITPACK(PW2.x, PW2.y, hp0, lp0); SPLITPACK(PW2.z, PW2.w, hp1, lp1);
            *reinterpret_cast<uint2*>(sm + 10240 + (rW0 + 64) * 80 + jW * 8) = make_uint2(hp0, hp1);
            *reinterpret_cast<uint2*>(sm + 20480 + (rW0 + 64) * 80 + jW * 8) = make_uint2(lp0, lp1);
            SPLITPACK(PW3.x, PW3.y, hp0, lp0); SPLITPACK(PW3.z, PW3.w, hp1, lp1);
            *reinterpret_cast<uint2*>(sm + 10240 + (rW0 + 96) * 80 + jW * 8) = make_uint2(hp0, hp1);
            *reinterpret_cast<uint2*>(sm + 20480 + (rW0 + 96) * 80 + jW * 8) = make_uint2(lp0, lp1);
        }
        __syncthreads();                       // smem chunk ready
        if (cc + 1 < NCHUNK) PRELOAD(cc + 1)   // loads in flight during MMAs
        DEC_KS(0u)
        DEC_KS(32u)
    }
#undef PRELOAD

    DEPI(0, 0) DEPI(0, 1) DEPI(0, 2) DEPI(0, 3)
    DEPI(1, 0) DEPI(1, 1) DEPI(1, 2) DEPI(1, 3)
}

// ---------------- launch ------------------------------------------------------
extern "C" void kernel_launch(void* const* d_in, const int* in_sizes, int n_in,
                              void* d_out, int out_size) {
    const float* x     = (const float*)d_in[0];
    const int*   xedge = (const int*)d_in[1];      // int32 [2, E]
    const float* w1l   = (const float*)d_in[2];
    const float* b1l   = (const float*)d_in[3];
    const float* w1r   = (const float*)d_in[4];
    const float* w2l   = (const float*)d_in[5];
    const float* b2l   = (const float*)d_in[6];
    const float* w2r   = (const float*)d_in[7];
    const float* wdec  = (const float*)d_in[8];
    const float* bdec  = (const float*)d_in[9];

    float* out_h  = (float*)d_out;
    float* out_dx = out_h + (size_t)N_NODES * F;

    const int agg_blocks = (N_NODES + 7) / 8;          // 12500
    const int mma_blocks = (N_NODES + 63) / 64;        // 1563

    // CSR build
    zero_kernel<<<(N_NODES + 255) / 256, 256>>>();
    hist_kernel<<<(N_EDGES + 255) / 256, 256>>>(xedge);
    scan1_kernel<<<NB_SCAN, SCAN_B>>>();
    scan2_kernel<<<1, 256>>>();
    scan3_kernel<<<NB_SCAN, SCAN_B>>>();
    fill_kernel<<<(N_EDGES + 255) / 256, 256>>>(xedge);

    // Layer 1: agg(x) -> g_agg; g_h1 = relu(g_agg@w1l^T + b1l + x@w1r^T)
    agg_kernel<0><<<agg_blocks, 256>>>(x);
    layer_mma<1><<<mma_blocks, 256>>>(x, w1l, w1r, b1l, nullptr, N_NODES);

    // Layer 2: agg(g_h1) -> g_agg; out_h = g_agg@w2l^T + b2l + g_h1@w2r^T
    agg_kernel<1><<<agg_blocks, 256>>>(nullptr);
    layer_mma<2><<<mma_blocks, 256>>>(nullptr, w2l, w2r, b2l, out_h, N_NODES);

    // Decoder: out_dx = out_h@wdec^T + bdec
    layer_mma<3><<<mma_blocks, 256>>>(out_h, wdec, nullptr, bdec, out_dx, N_NODES);
}

// round 14
// speedup vs baseline: 1.2530x; 1.0304x over previous
#include <cuda_runtime.h>
#include <cuda_bf16.h>

#define N_NODES 100000
#define N_EDGES 600000
#define F 128
#define SCAN_B 512
#define NB_SCAN ((N_NODES + SCAN_B - 1) / SCAN_B)   // 196

// ---------------- scratch (device globals: proven-safe classes) ---------------
__device__ int   g_deg[N_NODES];
__device__ int   g_cur[N_NODES];
__device__ int   g_off[N_NODES + 1];
__device__ int   g_srcs[N_EDGES];
__device__ int   g_bsum[256];
__device__ float g_agg[(size_t)N_NODES * F];
__device__ float g_h1 [(size_t)N_NODES * F];
// packed bf16 planes of the 5 weights: [w][ck][row][16 uints] (hi and lo)
__device__ unsigned g_wpkh[5 * 4 * 128 * 16];
__device__ unsigned g_wpkl[5 * 4 * 128 * 16];

// ---------------- CSR build ---------------------------------------------------
__global__ void zero_kernel() {
    int i = blockIdx.x * blockDim.x + threadIdx.x;
    if (i < N_NODES) g_deg[i] = 0;
}

__global__ void hist_kernel(const int* __restrict__ edges) {
    int i = blockIdx.x * blockDim.x + threadIdx.x;
    if (i < N_EDGES) {
        unsigned d = (unsigned)edges[N_EDGES + i];
        if (d < N_NODES) atomicAdd(&g_deg[d], 1);
    }
}

__global__ void scan1_kernel() {
    __shared__ int s[SCAN_B];
    int i = blockIdx.x * SCAN_B + threadIdx.x;
    int v = (i < N_NODES) ? g_deg[i] : 0;
    s[threadIdx.x] = v;
    __syncthreads();
    for (int off = 1; off < SCAN_B; off <<= 1) {
        int t = (threadIdx.x >= off) ? s[threadIdx.x - off] : 0;
        __syncthreads();
        s[threadIdx.x] += t;
        __syncthreads();
    }
    if (i < N_NODES) g_off[i] = s[threadIdx.x] - v;
    if (threadIdx.x == SCAN_B - 1) g_bsum[blockIdx.x] = s[SCAN_B - 1];
}

__global__ void scan2_kernel() {
    __shared__ int s[256];
    int t = threadIdx.x;
    int v = (t < NB_SCAN) ? g_bsum[t] : 0;
    s[t] = v;
    __syncthreads();
    for (int off = 1; off < 256; off <<= 1) {
        int u = (t >= off) ? s[t - off] : 0;
        __syncthreads();
        s[t] += u;
        __syncthreads();
    }
    if (t < NB_SCAN) g_bsum[t] = s[t] - v;
    if (t == 255) g_off[N_NODES] = s[255];
}

__global__ void scan3_kernel() {
    int i = blockIdx.x * SCAN_B + threadIdx.x;
    if (i < N_NODES) {
        int o = g_off[i] + g_bsum[blockIdx.x];
        g_off[i] = o;
        g_cur[i] = o;          // absolute write cursor for fill
    }
}

__global__ void fill_kernel(const int* __restrict__ edges) {
    int i = blockIdx.x * blockDim.x + threadIdx.x;
    if (i < N_EDGES) {
        unsigned s = (unsigned)edges[i];
        unsigned d = (unsigned)edges[N_EDGES + i];
        if (s < N_NODES && d < N_NODES) {
            int p = atomicAdd(&g_cur[d], 1);
            g_srcs[p] = (int)s;
        }
    }
}

// ---------------- helpers ------------------------------------------------------
#define SPLITPACK(vx, vy, hp_, lp_) { \
    __nv_bfloat16 h0_ = __float2bfloat16_rn(vx); \
    __nv_bfloat16 h1_ = __float2bfloat16_rn(vy); \
    __nv_bfloat16 l0_ = __float2bfloat16_rn((vx) - __bfloat162float(h0_)); \
    __nv_bfloat16 l1_ = __float2bfloat16_rn((vy) - __bfloat162float(h1_)); \
    hp_ = (unsigned)__bfloat16_as_ushort(h0_) | ((unsigned)__bfloat16_as_ushort(h1_) << 16); \
    lp_ = (unsigned)__bfloat16_as_ushort(l0_) | ((unsigned)__bfloat16_as_ushort(l1_) << 16); }

// ---------------- W pre-pack: 5 weights -> packed bf16 hi/lo planes -----------
// element (w, row, k4): float4 at w[row*32 + k4]; dst uint2 at
// (((w*4 + (k4>>3))*128 + row)*8 + (k4&7)) in uint2 units.
__global__ void wpack_kernel(const float* __restrict__ w1l, const float* __restrict__ w1r,
                             const float* __restrict__ w2l, const float* __restrict__ w2r,
                             const float* __restrict__ wdec) {
    int t = blockIdx.x * blockDim.x + threadIdx.x;
    if (t >= 5 * 128 * 32) return;
    int w = t >> 12, rem = t & 4095;
    int row = rem >> 5, k4 = rem & 31;
    const float* wp;
    if      (w == 0) wp = w1l;
    else if (w == 1) wp = w1r;
    else if (w == 2) wp = w2l;
    else if (w == 3) wp = w2r;
    else             wp = wdec;
    float4 v = reinterpret_cast<const float4*>(wp)[row * 32 + k4];
    unsigned hp0, lp0, hp1, lp1;
    SPLITPACK(v.x, v.y, hp0, lp0);
    SPLITPACK(v.z, v.w, hp1, lp1);
    size_t u2 = ((size_t)((w * 4 + (k4 >> 3)) * 128 + row) * 8 + (k4 & 7));
    reinterpret_cast<uint2*>(g_wpkh)[u2] = make_uint2(hp0, hp1);
    reinterpret_cast<uint2*>(g_wpkl)[u2] = make_uint2(lp0, lp1);
}

// ---------------- mean aggregation: one warp per node, 4-way MLP unroll -------
template <int SRC_SEL>
__global__ void agg_kernel(const float* __restrict__ in) {
    int w = (blockIdx.x * blockDim.x + threadIdx.x) >> 5;
    if (w >= N_NODES) return;
    int lane = threadIdx.x & 31;
    int beg = g_off[w], end = g_off[w + 1];
    const float* src = (SRC_SEL == 0) ? in : (const float*)g_h1;
    const float4* in4 = reinterpret_cast<const float4*>(src);
    float x0 = 0.f, x1 = 0.f, x2 = 0.f, x3 = 0.f;
    int e = beg;
    for (; e + 4 <= end; e += 4) {
        int s0 = g_srcs[e], s1 = g_srcs[e + 1], s2 = g_srcs[e + 2], s3 = g_srcs[e + 3];
        float4 v0 = in4[(size_t)s0 * 32 + lane];
        float4 v1 = in4[(size_t)s1 * 32 + lane];
        float4 v2 = in4[(size_t)s2 * 32 + lane];
        float4 v3 = in4[(size_t)s3 * 32 + lane];
        x0 += v0.x + v1.x + v2.x + v3.x;
        x1 += v0.y + v1.y + v2.y + v3.y;
        x2 += v0.z + v1.z + v2.z + v3.z;
        x3 += v0.w + v1.w + v2.w + v3.w;
    }
    for (; e < end; e++) {
        int s = g_srcs[e];
        float4 v = in4[(size_t)s * 32 + lane];
        x0 += v.x; x1 += v.y; x2 += v.z; x3 += v.w;
    }
    int d = end - beg;
    float inv = (d > 0) ? (1.0f / (float)d) : 0.0f;
    float4 r; r.x = x0 * inv; r.y = x1 * inv; r.z = x2 * inv; r.w = x3 * inv;
    reinterpret_cast<float4*>(g_agg)[(size_t)w * 32 + lane] = r;
}

// ---------------- mma.sync bf16-split GEMM (64-row tile + reg prefetch) -------
// smem: Ah[0,5120) Al[5120,10240) Wh[10240,20480) Wl[20480,30720); stride 80B.
#define MMAS(c0, c1, c2, c3, a0, a1, a2, a3, b0, b1) \
    asm volatile("mma.sync.aligned.m16n8k16.row.col.f32.bf16.bf16.f32 " \
        "{%0,%1,%2,%3}, {%4,%5,%6,%7}, {%8,%9}, {%0,%1,%2,%3};" \
        : "+f"(c0), "+f"(c1), "+f"(c2), "+f"(c3) \
        : "r"(a0), "r"(a1), "r"(a2), "r"(a3), "r"(b0), "r"(b1))

#define DACC(mt, nt) \
    float C##mt##nt##_0 = 0.f, C##mt##nt##_1 = 0.f, C##mt##nt##_2 = 0.f, C##mt##nt##_3 = 0.f

#define LDA(mt) \
    unsigned AH##mt##_0, AH##mt##_1, AH##mt##_2, AH##mt##_3; \
    unsigned AL##mt##_0, AL##mt##_1, AL##mt##_2, AL##mt##_3; \
    { unsigned o_ = aBase + (unsigned)(mt * 16 * 80) + kb; \
      AH##mt##_0 = *reinterpret_cast<const unsigned*>(sm + o_); \
      AH##mt##_1 = *reinterpret_cast<const unsigned*>(sm + o_ + 640); \
      AH##mt##_2 = *reinterpret_cast<const unsigned*>(sm + o_ + 16); \
      AH##mt##_3 = *reinterpret_cast<const unsigned*>(sm + o_ + 656); \
      AL##mt##_0 = *reinterpret_cast<const unsigned*>(sm + o_ + 5120); \
      AL##mt##_1 = *reinterpret_cast<const unsigned*>(sm + o_ + 5760); \
      AL##mt##_2 = *reinterpret_cast<const unsigned*>(sm + o_ + 5136); \
      AL##mt##_3 = *reinterpret_cast<const unsigned*>(sm + o_ + 5776); }

#define LDW(nt) \
    unsigned WH##nt##_0, WH##nt##_1, WL##nt##_0, WL##nt##_1; \
    { unsigned o_ = wBase + (unsigned)(nt * 8 * 80) + kb; \
      WH##nt##_0 = *reinterpret_cast<const unsigned*>(sm + o_); \
      WH##nt##_1 = *reinterpret_cast<const unsigned*>(sm + o_ + 16); \
      WL##nt##_0 = *reinterpret_cast<const unsigned*>(sm + o_ + 10240); \
      WL##nt##_1 = *reinterpret_cast<const unsigned*>(sm + o_ + 10256); }

#define DOMMA(mt, nt) \
    MMAS(C##mt##nt##_0, C##mt##nt##_1, C##mt##nt##_2, C##mt##nt##_3, \
         AH##mt##_0, AH##mt##_1, AH##mt##_2, AH##mt##_3, WH##nt##_0, WH##nt##_1); \
    MMAS(C##mt##nt##_0, C##mt##nt##_1, C##mt##nt##_2, C##mt##nt##_3, \
         AH##mt##_0, AH##mt##_1, AH##mt##_2, AH##mt##_3, WL##nt##_0, WL##nt##_1); \
    MMAS(C##mt##nt##_0, C##mt##nt##_1, C##mt##nt##_2, C##mt##nt##_3, \
         AL##mt##_0, AL##mt##_1, AL##mt##_2, AL##mt##_3, WH##nt##_0, WH##nt##_1)

#define DEC_KS(kb_) { \
    unsigned kb = (kb_); \
    LDA(0) LDA(1) LDW(0) LDW(1) LDW(2) LDW(3) \
    DOMMA(0, 0); DOMMA(0, 1); DOMMA(0, 2); DOMMA(0, 3); \
    DOMMA(1, 0); DOMMA(1, 1); DOMMA(1, 2); DOMMA(1, 3); }

#define DEPI(mt, nt) { \
    int nc = wn * 32 + nt * 8 + 2 * r4; \
    int m = m0 + wm * 32 + mt * 16 + q4; \
    float v0 = C##mt##nt##_0 + bias[nc], v1 = C##mt##nt##_1 + bias[nc + 1]; \
    float v2 = C##mt##nt##_2 + bias[nc], v3 = C##mt##nt##_3 + bias[nc + 1]; \
    if (RELU) { v0 = fmaxf(v0, 0.f); v1 = fmaxf(v1, 0.f); \
                v2 = fmaxf(v2, 0.f); v3 = fmaxf(v3, 0.f); } \
    if (m < n) *reinterpret_cast<float2*>(&out[(size_t)m * F + nc]) = make_float2(v0, v1); \
    if (m + 8 < n) *reinterpret_cast<float2*>(&out[(size_t)(m + 8) * F + nc]) = make_float2(v2, v3); }

// CFG 1: out(g_h1) = relu(g_agg@w1l^T + b + x(param a2)@w1r^T)  [weights 0,1]
// CFG 2: out(param) = g_agg@w2l^T + b + g_h1@w2r^T              [weights 2,3]
// CFG 3: out(param) = a2(param)@wdec^T + b                      [weight 4]
template <int CFG>
__global__ void __launch_bounds__(256)
layer_mma(const float* __restrict__ a2p, const float* __restrict__ bias,
          float* __restrict__ outp, int n) {
    __shared__ __align__(16) char sm[30720];

    const bool RELU = (CFG == 1);
    const int NPASS = (CFG == 3) ? 1 : 2;
    const int NCHUNK = NPASS * 4;
    float* out = (CFG == 1) ? (float*)g_h1 : outp;

    int tid = threadIdx.x, lane = tid & 31, wid = tid >> 5;
    int wm = wid & 1, wn = wid >> 1;           // 2 m-warps x 4 n-warps
    int q4 = lane >> 2, r4 = lane & 3;
    int m0 = blockIdx.x * 64;

    DACC(0, 0); DACC(0, 1); DACC(0, 2); DACC(0, 3);
    DACC(1, 0); DACC(1, 1); DACC(1, 2); DACC(1, 3);

    unsigned aBase = (unsigned)((wm * 32 + q4) * 80 + r4 * 4);
    unsigned wBase = (unsigned)(10240 + (wn * 32 + q4) * 80 + r4 * 4);

    // loader coordinates (fixed per thread)
    int fA0 = tid * 2, fA1 = tid * 2 + 1;
    int rA0 = fA0 >> 3, jA0 = fA0 & 7;
    int rA1 = fA1 >> 3, jA1 = fA1 & 7;
    int rWa = tid >> 2, qWa = tid & 3;         // uint4 coords: rows tid>>2 and +64
    // prefetch registers
    float4 PA0, PA1;
    uint4  PW0, PW1, PW2, PW3;                 // Wh rows a/b, Wl rows a/b

#define PRELOAD(cc_) { \
        int p_ = (cc_) >> 2, ck_ = (cc_) & 3; \
        const float* ap_; \
        if (CFG == 3)      ap_ = a2p; \
        else if (p_ == 0)  ap_ = (const float*)g_agg; \
        else if (CFG == 1) ap_ = a2p; \
        else               ap_ = (const float*)g_h1; \
        int wi_; \
        if (CFG == 1)      wi_ = p_; \
        else if (CFG == 2) wi_ = 2 + p_; \
        else               wi_ = 4; \
        const float4* a4_ = reinterpret_cast<const float4*>(ap_); \
        const uint4* wh4_ = reinterpret_cast<const uint4*>(g_wpkh) + (size_t)(wi_ * 4 + ck_) * 512; \
        const uint4* wl4_ = reinterpret_cast<const uint4*>(g_wpkl) + (size_t)(wi_ * 4 + ck_) * 512; \
        PA0 = (m0 + rA0 < n) ? a4_[(size_t)(m0 + rA0) * 32 + ck_ * 8 + jA0] \
                             : make_float4(0.f, 0.f, 0.f, 0.f); \
        PA1 = (m0 + rA1 < n) ? a4_[(size_t)(m0 + rA1) * 32 + ck_ * 8 + jA1] \
                             : make_float4(0.f, 0.f, 0.f, 0.f); \
        PW0 = wh4_[tid]; \
        PW1 = wh4_[tid + 256]; \
        PW2 = wl4_[tid]; \
        PW3 = wl4_[tid + 256]; }

    PRELOAD(0)
    for (int cc = 0; cc < NCHUNK; cc++) {
        __syncthreads();                       // smem free (prev compute done)
        {
            unsigned hp0, lp0, hp1, lp1;
            SPLITPACK(PA0.x, PA0.y, hp0, lp0); SPLITPACK(PA0.z, PA0.w, hp1, lp1);
            *reinterpret_cast<uint2*>(sm + rA0 * 80 + jA0 * 8) = make_uint2(hp0, hp1);
            *reinterpret_cast<uint2*>(sm + 5120 + rA0 * 80 + jA0 * 8) = make_uint2(lp0, lp1);
            SPLITPACK(PA1.x, PA1.y, hp0, lp0); SPLITPACK(PA1.z, PA1.w, hp1, lp1);
            *reinterpret_cast<uint2*>(sm + rA1 * 80 + jA1 * 8) = make_uint2(hp0, hp1);
            *reinterpret_cast<uint2*>(sm + 5120 + rA1 * 80 + jA1 * 8) = make_uint2(lp0, lp1);
            *reinterpret_cast<uint4*>(sm + 10240 + rWa * 80 + qWa * 16) = PW0;
            *reinterpret_cast<uint4*>(sm + 10240 + (rWa + 64) * 80 + qWa * 16) = PW1;
            *reinterpret_cast<uint4*>(sm + 20480 + rWa * 80 + qWa * 16) = PW2;
            *reinterpret_cast<uint4*>(sm + 20480 + (rWa + 64) * 80 + qWa * 16) = PW3;
        }
        __syncthreads();                       // smem chunk ready
        if (cc + 1 < NCHUNK) PRELOAD(cc + 1)   // loads in flight during MMAs
        DEC_KS(0u)
        DEC_KS(32u)
    }
#undef PRELOAD

    DEPI(0, 0) DEPI(0, 1) DEPI(0, 2) DEPI(0, 3)
    DEPI(1, 0) DEPI(1, 1) DEPI(1, 2) DEPI(1, 3)
}

// ---------------- launch ------------------------------------------------------
extern "C" void kernel_launch(void* const* d_in, const int* in_sizes, int n_in,
                              void* d_out, int out_size) {
    const float* x     = (const float*)d_in[0];
    const int*   xedge = (const int*)d_in[1];      // int32 [2, E]
    const float* w1l   = (const float*)d_in[2];
    const float* b1l   = (const float*)d_in[3];
    const float* w1r   = (const float*)d_in[4];
    const float* w2l   = (const float*)d_in[5];
    const float* b2l   = (const float*)d_in[6];
    const float* w2r   = (const float*)d_in[7];
    const float* wdec  = (const float*)d_in[8];
    const float* bdec  = (const float*)d_in[9];

    float* out_h  = (float*)d_out;
    float* out_dx = out_h + (size_t)N_NODES * F;

    const int agg_blocks = (N_NODES + 7) / 8;          // 12500
    const int mma_blocks = (N_NODES + 63) / 64;        // 1563

    // CSR build + weight packing (independent streams of work, all capturable)
    zero_kernel<<<(N_NODES + 255) / 256, 256>>>();
    wpack_kernel<<<(5 * 128 * 32 + 255) / 256, 256>>>(w1l, w1r, w2l, w2r, wdec);
    hist_kernel<<<(N_EDGES + 255) / 256, 256>>>(xedge);
    scan1_kernel<<<NB_SCAN, SCAN_B>>>();
    scan2_kernel<<<1, 256>>>();
    scan3_kernel<<<NB_SCAN, SCAN_B>>>();
    fill_kernel<<<(N_EDGES + 255) / 256, 256>>>(xedge);

    // Layer 1: agg(x) -> g_agg; g_h1 = relu(g_agg@w1l^T + b1l + x@w1r^T)
    agg_kernel<0><<<agg_blocks, 256>>>(x);
    layer_mma<1><<<mma_blocks, 256>>>(x, b1l, nullptr, N_NODES);

    // Layer 2: agg(g_h1) -> g_agg; out_h = g_agg@w2l^T + b2l + g_h1@w2r^T
    agg_kernel<1><<<agg_blocks, 256>>>(nullptr);
    layer_mma<2><<<mma_blocks, 256>>>(nullptr, b2l, out_h, N_NODES);

    // Decoder: out_dx = out_h@wdec^T + bdec
    layer_mma<3><<<mma_blocks, 256>>>(out_h, bdec, out_dx, N_NODES);
}

// round 16
// speedup vs baseline: 1.2635x; 1.0084x over previous
#include <cuda_runtime.h>
#include <cuda_bf16.h>

#define N_NODES 100000
#define N_EDGES 600000
#define F 128
#define SCAN_B 512
#define NB_SCAN ((N_NODES + SCAN_B - 1) / SCAN_B)   // 196
#define ZERO_BLOCKS 391                              // 391*256 >= N_NODES

// ---------------- scratch (device globals: proven-safe classes) ---------------
__device__ int   g_deg[N_NODES];
__device__ int   g_cur[N_NODES];
__device__ int   g_off[N_NODES + 1];
__device__ int   g_srcs[N_EDGES];
__device__ int   g_bsum[256];
__device__ float g_agg[(size_t)N_NODES * F];
__device__ float g_h1 [(size_t)N_NODES * F];
// packed bf16 planes of the 5 weights: [w][ck][row][16 uints] (hi and lo)
__device__ unsigned g_wpkh[5 * 4 * 128 * 16];
__device__ unsigned g_wpkl[5 * 4 * 128 * 16];

// ---------------- helpers ------------------------------------------------------
#define SPLITPACK(vx, vy, hp_, lp_) { \
    __nv_bfloat16 h0_ = __float2bfloat16_rn(vx); \
    __nv_bfloat16 h1_ = __float2bfloat16_rn(vy); \
    __nv_bfloat16 l0_ = __float2bfloat16_rn((vx) - __bfloat162float(h0_)); \
    __nv_bfloat16 l1_ = __float2bfloat16_rn((vy) - __bfloat162float(h1_)); \
    hp_ = (unsigned)__bfloat16_as_ushort(h0_) | ((unsigned)__bfloat16_as_ushort(h1_) << 16); \
    lp_ = (unsigned)__bfloat16_as_ushort(l0_) | ((unsigned)__bfloat16_as_ushort(l1_) << 16); }

// ---------------- prep: zero g_deg + pack weights (fused) ---------------------
__global__ void prep_kernel(const float* __restrict__ w1l, const float* __restrict__ w1r,
                            const float* __restrict__ w2l, const float* __restrict__ w2r,
                            const float* __restrict__ wdec) {
    int b = blockIdx.x;
    if (b < ZERO_BLOCKS) {
        int i = b * 256 + threadIdx.x;
        if (i < N_NODES) g_deg[i] = 0;
    } else {
        int t = (b - ZERO_BLOCKS) * 256 + threadIdx.x;
        if (t >= 5 * 128 * 32) return;
        int w = t >> 12, rem = t & 4095;
        int row = rem >> 5, k4 = rem & 31;
        const float* wp;
        if      (w == 0) wp = w1l;
        else if (w == 1) wp = w1r;
        else if (w == 2) wp = w2l;
        else if (w == 3) wp = w2r;
        else             wp = wdec;
        float4 v = reinterpret_cast<const float4*>(wp)[row * 32 + k4];
        unsigned hp0, lp0, hp1, lp1;
        SPLITPACK(v.x, v.y, hp0, lp0);
        SPLITPACK(v.z, v.w, hp1, lp1);
        size_t u2 = ((size_t)((w * 4 + (k4 >> 3)) * 128 + row) * 8 + (k4 & 7));
        reinterpret_cast<uint2*>(g_wpkh)[u2] = make_uint2(hp0, hp1);
        reinterpret_cast<uint2*>(g_wpkl)[u2] = make_uint2(lp0, lp1);
    }
}

// ---------------- CSR build ---------------------------------------------------
__global__ void hist_kernel(const int* __restrict__ edges) {
    int i = blockIdx.x * blockDim.x + threadIdx.x;
    if (i < N_EDGES) {
        unsigned d = (unsigned)edges[N_EDGES + i];
        if (d < N_NODES) atomicAdd(&g_deg[d], 1);
    }
}

__global__ void scan1_kernel() {
    __shared__ int s[SCAN_B];
    int i = blockIdx.x * SCAN_B + threadIdx.x;
    int v = (i < N_NODES) ? g_deg[i] : 0;
    s[threadIdx.x] = v;
    __syncthreads();
    for (int off = 1; off < SCAN_B; off <<= 1) {
        int t = (threadIdx.x >= off) ? s[threadIdx.x - off] : 0;
        __syncthreads();
        s[threadIdx.x] += t;
        __syncthreads();
    }
    if (i < N_NODES) g_off[i] = s[threadIdx.x] - v;
    if (threadIdx.x == SCAN_B - 1) g_bsum[blockIdx.x] = s[SCAN_B - 1];
}

__global__ void scan2_kernel() {
    __shared__ int s[256];
    int t = threadIdx.x;
    int v = (t < NB_SCAN) ? g_bsum[t] : 0;
    s[t] = v;
    __syncthreads();
    for (int off = 1; off < 256; off <<= 1) {
        int u = (t >= off) ? s[t - off] : 0;
        __syncthreads();
        s[t] += u;
        __syncthreads();
    }
    if (t < NB_SCAN) g_bsum[t] = s[t] - v;
    if (t == 255) g_off[N_NODES] = s[255];
}

__global__ void scan3_kernel() {
    int i = blockIdx.x * SCAN_B + threadIdx.x;
    if (i < N_NODES) {
        int o = g_off[i] + g_bsum[blockIdx.x];
        g_off[i] = o;
        g_cur[i] = o;          // absolute write cursor for fill
    }
}

__global__ void fill_kernel(const int* __restrict__ edges) {
    int i = blockIdx.x * blockDim.x + threadIdx.x;
    if (i < N_EDGES) {
        unsigned s = (unsigned)edges[i];
        unsigned d = (unsigned)edges[N_EDGES + i];
        if (s < N_NODES && d < N_NODES) {
            int p = atomicAdd(&g_cur[d], 1);
            g_srcs[p] = (int)s;
        }
    }
}

// ---------------- mean aggregation: one warp per node, 4-way MLP unroll -------
template <int SRC_SEL>
__global__ void agg_kernel(const float* __restrict__ in) {
    int w = (blockIdx.x * blockDim.x + threadIdx.x) >> 5;
    if (w >= N_NODES) return;
    int lane = threadIdx.x & 31;
    int beg = g_off[w], end = g_off[w + 1];
    const float* src = (SRC_SEL == 0) ? in : (const float*)g_h1;
    const float4* in4 = reinterpret_cast<const float4*>(src);
    float x0 = 0.f, x1 = 0.f, x2 = 0.f, x3 = 0.f;
    int e = beg;
    for (; e + 4 <= end; e += 4) {
        int s0 = g_srcs[e], s1 = g_srcs[e + 1], s2 = g_srcs[e + 2], s3 = g_srcs[e + 3];
        float4 v0 = in4[(size_t)s0 * 32 + lane];
        float4 v1 = in4[(size_t)s1 * 32 + lane];
        float4 v2 = in4[(size_t)s2 * 32 + lane];
        float4 v3 = in4[(size_t)s3 * 32 + lane];
        x0 += v0.x + v1.x + v2.x + v3.x;
        x1 += v0.y + v1.y + v2.y + v3.y;
        x2 += v0.z + v1.z + v2.z + v3.z;
        x3 += v0.w + v1.w + v2.w + v3.w;
    }
    for (; e < end; e++) {
        int s = g_srcs[e];
        float4 v = in4[(size_t)s * 32 + lane];
        x0 += v.x; x1 += v.y; x2 += v.z; x3 += v.w;
    }
    int d = end - beg;
    float inv = (d > 0) ? (1.0f / (float)d) : 0.0f;
    float4 r; r.x = x0 * inv; r.y = x1 * inv; r.z = x2 * inv; r.w = x3 * inv;
    reinterpret_cast<float4*>(g_agg)[(size_t)w * 32 + lane] = r;
}

// ---------------- mma.sync bf16-split GEMM (64-row tile + reg prefetch) -------
// smem: Ah[0,5120) Al[5120,10240) Wh[10240,20480) Wl[20480,30720); stride 80B.
#define MMAS(c0, c1, c2, c3, a0, a1, a2, a3, b0, b1) \
    asm volatile("mma.sync.aligned.m16n8k16.row.col.f32.bf16.bf16.f32 " \
        "{%0,%1,%2,%3}, {%4,%5,%6,%7}, {%8,%9}, {%0,%1,%2,%3};" \
        : "+f"(c0), "+f"(c1), "+f"(c2), "+f"(c3) \
        : "r"(a0), "r"(a1), "r"(a2), "r"(a3), "r"(b0), "r"(b1))

#define DACC_P(P, mt, nt) \
    float P##mt##nt##_0 = 0.f, P##mt##nt##_1 = 0.f, P##mt##nt##_2 = 0.f, P##mt##nt##_3 = 0.f

#define LDA(mt) \
    unsigned AH##mt##_0, AH##mt##_1, AH##mt##_2, AH##mt##_3; \
    unsigned AL##mt##_0, AL##mt##_1, AL##mt##_2, AL##mt##_3; \
    { unsigned o_ = aBase + (unsigned)(mt * 16 * 80) + kb; \
      AH##mt##_0 = *reinterpret_cast<const unsigned*>(sm + o_); \
      AH##mt##_1 = *reinterpret_cast<const unsigned*>(sm + o_ + 640); \
      AH##mt##_2 = *reinterpret_cast<const unsigned*>(sm + o_ + 16); \
      AH##mt##_3 = *reinterpret_cast<const unsigned*>(sm + o_ + 656); \
      AL##mt##_0 = *reinterpret_cast<const unsigned*>(sm + o_ + 5120); \
      AL##mt##_1 = *reinterpret_cast<const unsigned*>(sm + o_ + 5760); \
      AL##mt##_2 = *reinterpret_cast<const unsigned*>(sm + o_ + 5136); \
      AL##mt##_3 = *reinterpret_cast<const unsigned*>(sm + o_ + 5776); }

#define LDW(nt) \
    unsigned WH##nt##_0, WH##nt##_1, WL##nt##_0, WL##nt##_1; \
    { unsigned o_ = wBase + (unsigned)(nt * 8 * 80) + kb; \
      WH##nt##_0 = *reinterpret_cast<const unsigned*>(sm + o_); \
      WH##nt##_1 = *reinterpret_cast<const unsigned*>(sm + o_ + 16); \
      WL##nt##_0 = *reinterpret_cast<const unsigned*>(sm + o_ + 10240); \
      WL##nt##_1 = *reinterpret_cast<const unsigned*>(sm + o_ + 10256); }

#define DOMMA_P(P, mt, nt) \
    MMAS(P##mt##nt##_0, P##mt##nt##_1, P##mt##nt##_2, P##mt##nt##_3, \
         AH##mt##_0, AH##mt##_1, AH##mt##_2, AH##mt##_3, WH##nt##_0, WH##nt##_1); \
    MMAS(P##mt##nt##_0, P##mt##nt##_1, P##mt##nt##_2, P##mt##nt##_3, \
         AH##mt##_0, AH##mt##_1, AH##mt##_2, AH##mt##_3, WL##nt##_0, WL##nt##_1); \
    MMAS(P##mt##nt##_0, P##mt##nt##_1, P##mt##nt##_2, P##mt##nt##_3, \
         AL##mt##_0, AL##mt##_1, AL##mt##_2, AL##mt##_3, WH##nt##_0, WH##nt##_1)

#define DEC_KS_P(P, kb_) { \
    unsigned kb = (kb_); \
    LDA(0) LDA(1) LDW(0) LDW(1) LDW(2) LDW(3) \
    DOMMA_P(P, 0, 0); DOMMA_P(P, 0, 1); DOMMA_P(P, 0, 2); DOMMA_P(P, 0, 3); \
    DOMMA_P(P, 1, 0); DOMMA_P(P, 1, 1); DOMMA_P(P, 1, 2); DOMMA_P(P, 1, 3); }

#define DEPI_P(P, mt, nt, BIASP, OUTP, DORELU) { \
    int nc = wn * 32 + nt * 8 + 2 * r4; \
    int m = m0 + wm * 32 + mt * 16 + q4; \
    float v0 = P##mt##nt##_0 + (BIASP)[nc], v1 = P##mt##nt##_1 + (BIASP)[nc + 1]; \
    float v2 = P##mt##nt##_2 + (BIASP)[nc], v3 = P##mt##nt##_3 + (BIASP)[nc + 1]; \
    if (DORELU) { v0 = fmaxf(v0, 0.f); v1 = fmaxf(v1, 0.f); \
                  v2 = fmaxf(v2, 0.f); v3 = fmaxf(v3, 0.f); } \
    if (m < n) *reinterpret_cast<float2*>(&(OUTP)[(size_t)m * F + nc]) = make_float2(v0, v1); \
    if (m + 8 < n) *reinterpret_cast<float2*>(&(OUTP)[(size_t)(m + 8) * F + nc]) = make_float2(v2, v3); }

// dx-phase: warp wn==ck applies bias to its h accs, writes h to global AND
// split-packs into A smem planes (chunk-local col = nt*8+2r4).
#define HWR(mt, nt) { \
    int ncl = nt * 16 + r4 * 4; \
    int ncg = wn * 32 + nt * 8 + 2 * r4; \
    int ml0 = wm * 32 + mt * 16 + q4; \
    float v0 = C##mt##nt##_0 + bias[ncg], v1 = C##mt##nt##_1 + bias[ncg + 1]; \
    float v2 = C##mt##nt##_2 + bias[ncg], v3 = C##mt##nt##_3 + bias[ncg + 1]; \
    unsigned hp_, lp_; \
    SPLITPACK(v0, v1, hp_, lp_); \
    *reinterpret_cast<unsigned*>(sm + ml0 * 80 + ncl) = hp_; \
    *reinterpret_cast<unsigned*>(sm + 5120 + ml0 * 80 + ncl) = lp_; \
    if (m0 + ml0 < n) \
        *reinterpret_cast<float2*>(&out[(size_t)(m0 + ml0) * F + ncg]) = make_float2(v0, v1); \
    SPLITPACK(v2, v3, hp_, lp_); \
    *reinterpret_cast<unsigned*>(sm + (ml0 + 8) * 80 + ncl) = hp_; \
    *reinterpret_cast<unsigned*>(sm + 5120 + (ml0 + 8) * 80 + ncl) = lp_; \
    if (m0 + ml0 + 8 < n) \
        *reinterpret_cast<float2*>(&out[(size_t)(m0 + ml0 + 8) * F + ncg]) = make_float2(v2, v3); }

// CFG 1: g_h1 = relu(g_agg@w1l^T + b1l + x(a2p)@w1r^T)            [weights 0,1]
// CFG 2: outp = g_agg@w2l^T + b2l + g_h1@w2r^T; out2 = h@wdec^T+b  [weights 2,3,4]
template <int CFG>
__global__ void __launch_bounds__(256)
layer_mma(const float* __restrict__ a2p, const float* __restrict__ bias,
          float* __restrict__ outp, const float* __restrict__ bias2,
          float* __restrict__ out2, int n) {
    __shared__ __align__(16) char sm[30720];

    const int NCHUNK = 8;
    float* out = (CFG == 1) ? (float*)g_h1 : outp;

    int tid = threadIdx.x, lane = tid & 31, wid = tid >> 5;
    int wm = wid & 1, wn = wid >> 1;           // 2 m-warps x 4 n-warps
    int q4 = lane >> 2, r4 = lane & 3;
    int m0 = blockIdx.x * 64;

    DACC_P(C, 0, 0); DACC_P(C, 0, 1); DACC_P(C, 0, 2); DACC_P(C, 0, 3);
    DACC_P(C, 1, 0); DACC_P(C, 1, 1); DACC_P(C, 1, 2); DACC_P(C, 1, 3);

    unsigned aBase = (unsigned)((wm * 32 + q4) * 80 + r4 * 4);
    unsigned wBase = (unsigned)(10240 + (wn * 32 + q4) * 80 + r4 * 4);

    // loader coordinates (fixed per thread)
    int fA0 = tid * 2, fA1 = tid * 2 + 1;
    int rA0 = fA0 >> 3, jA0 = fA0 & 7;
    int rA1 = fA1 >> 3, jA1 = fA1 & 7;
    int rWa = tid >> 2, qWa = tid & 3;         // uint4 coords: rows tid>>2 and +64
    float4 PA0, PA1;
    uint4  PW0, PW1, PW2, PW3;

#define PRELOAD(cc_) { \
        int p_ = (cc_) >> 2, ck_ = (cc_) & 3; \
        const float* ap_; \
        if (p_ == 0)       ap_ = (const float*)g_agg; \
        else if (CFG == 1) ap_ = a2p; \
        else               ap_ = (const float*)g_h1; \
        int wi_ = (CFG == 1) ? p_ : 2 + p_; \
        const float4* a4_ = reinterpret_cast<const float4*>(ap_); \
        const uint4* wh4_ = reinterpret_cast<const uint4*>(g_wpkh) + (size_t)(wi_ * 4 + ck_) * 512; \
        const uint4* wl4_ = reinterpret_cast<const uint4*>(g_wpkl) + (size_t)(wi_ * 4 + ck_) * 512; \
        PA0 = (m0 + rA0 < n) ? a4_[(size_t)(m0 + rA0) * 32 + ck_ * 8 + jA0] \
                             : make_float4(0.f, 0.f, 0.f, 0.f); \
        PA1 = (m0 + rA1 < n) ? a4_[(size_t)(m0 + rA1) * 32 + ck_ * 8 + jA1] \
                             : make_float4(0.f, 0.f, 0.f, 0.f); \
        PW0 = wh4_[tid]; \
        PW1 = wh4_[tid + 256]; \
        PW2 = wl4_[tid]; \
        PW3 = wl4_[tid + 256]; }

    PRELOAD(0)
    for (int cc = 0; cc < NCHUNK; cc++) {
        __syncthreads();
        {
            unsigned hp0, lp0, hp1, lp1;
            SPLITPACK(PA0.x, PA0.y, hp0, lp0); SPLITPACK(PA0.z, PA0.w, hp1, lp1);
            *reinterpret_cast<uint2*>(sm + rA0 * 80 + jA0 * 8) = make_uint2(hp0, hp1);
            *reinterpret_cast<uint2*>(sm + 5120 + rA0 * 80 + jA0 * 8) = make_uint2(lp0, lp1);
            SPLITPACK(PA1.x, PA1.y, hp0, lp0); SPLITPACK(PA1.z, PA1.w, hp1, lp1);
            *reinterpret_cast<uint2*>(sm + rA1 * 80 + jA1 * 8) = make_uint2(hp0, hp1);
            *reinterpret_cast<uint2*>(sm + 5120 + rA1 * 80 + jA1 * 8) = make_uint2(lp0, lp1);
            *reinterpret_cast<uint4*>(sm + 10240 + rWa * 80 + qWa * 16) = PW0;
            *reinterpret_cast<uint4*>(sm + 10240 + (rWa + 64) * 80 + qWa * 16) = PW1;
            *reinterpret_cast<uint4*>(sm + 20480 + rWa * 80 + qWa * 16) = PW2;
            *reinterpret_cast<uint4*>(sm + 20480 + (rWa + 64) * 80 + qWa * 16) = PW3;
        }
        __syncthreads();
        if (cc + 1 < NCHUNK) PRELOAD(cc + 1)
        DEC_KS_P(C, 0u)
        DEC_KS_P(C, 32u)
    }
#undef PRELOAD

    if (CFG == 1) {
        DEPI_P(C, 0, 0, bias, out, true) DEPI_P(C, 0, 1, bias, out, true)
        DEPI_P(C, 0, 2, bias, out, true) DEPI_P(C, 0, 3, bias, out, true)
        DEPI_P(C, 1, 0, bias, out, true) DEPI_P(C, 1, 1, bias, out, true)
        DEPI_P(C, 1, 2, bias, out, true) DEPI_P(C, 1, 3, bias, out, true)
    } else {
        // ---- fused decoder: dx = h@wdec^T + bdec ----
        DACC_P(D, 0, 0); DACC_P(D, 0, 1); DACC_P(D, 0, 2); DACC_P(D, 0, 3);
        DACC_P(D, 1, 0); DACC_P(D, 1, 1); DACC_P(D, 1, 2); DACC_P(D, 1, 3);
        for (int ck = 0; ck < 4; ck++) {
            __syncthreads();                   // prior chunk's MMA reads done
            if (wn == ck) {
                HWR(0, 0) HWR(0, 1) HWR(0, 2) HWR(0, 3)
                HWR(1, 0) HWR(1, 1) HWR(1, 2) HWR(1, 3)
            }
            {   // wdec chunk planes -> smem (weight index 4)
                const uint4* wh4_ = reinterpret_cast<const uint4*>(g_wpkh) + (size_t)(16 + ck) * 512;
                const uint4* wl4_ = reinterpret_cast<const uint4*>(g_wpkl) + (size_t)(16 + ck) * 512;
                *reinterpret_cast<uint4*>(sm + 10240 + rWa * 80 + qWa * 16) = wh4_[tid];
                *reinterpret_cast<uint4*>(sm + 10240 + (rWa + 64) * 80 + qWa * 16) = wh4_[tid + 256];
                *reinterpret_cast<uint4*>(sm + 20480 + rWa * 80 + qWa * 16) = wl4_[tid];
                *reinterpret_cast<uint4*>(sm + 20480 + (rWa + 64) * 80 + qWa * 16) = wl4_[tid + 256];
            }
            __syncthreads();
            DEC_KS_P(D, 0u)
            DEC_KS_P(D, 32u)
        }
        DEPI_P(D, 0, 0, bias2, out2, false) DEPI_P(D, 0, 1, bias2, out2, false)
        DEPI_P(D, 0, 2, bias2, out2, false) DEPI_P(D, 0, 3, bias2, out2, false)
        DEPI_P(D, 1, 0, bias2, out2, false) DEPI_P(D, 1, 1, bias2, out2, false)
        DEPI_P(D, 1, 2, bias2, out2, false) DEPI_P(D, 1, 3, bias2, out2, false)
    }
}

// ---------------- launch ------------------------------------------------------
extern "C" void kernel_launch(void* const* d_in, const int* in_sizes, int n_in,
                              void* d_out, int out_size) {
    const float* x     = (const float*)d_in[0];
    const int*   xedge = (const int*)d_in[1];      // int32 [2, E]
    const float* w1l   = (const float*)d_in[2];
    const float* b1l   = (const float*)d_in[3];
    const float* w1r   = (const float*)d_in[4];
    const float* w2l   = (const float*)d_in[5];
    const float* b2l   = (const float*)d_in[6];
    const float* w2r   = (const float*)d_in[7];
    const float* wdec  = (const float*)d_in[8];
    const float* bdec  = (const float*)d_in[9];

    float* out_h  = (float*)d_out;
    float* out_dx = out_h + (size_t)N_NODES * F;

    const int agg_blocks = (N_NODES + 7) / 8;          // 12500
    const int mma_blocks = (N_NODES + 63) / 64;        // 1563

    // prep (zero deg + pack weights) then CSR build
    prep_kernel<<<ZERO_BLOCKS + 80, 256>>>(w1l, w1r, w2l, w2r, wdec);
    hist_kernel<<<(N_EDGES + 255) / 256, 256>>>(xedge);
    scan1_kernel<<<NB_SCAN, SCAN_B>>>();
    scan2_kernel<<<1, 256>>>();
    scan3_kernel<<<NB_SCAN, SCAN_B>>>();
    fill_kernel<<<(N_EDGES + 255) / 256, 256>>>(xedge);

    // Layer 1: agg(x) -> g_agg; g_h1 = relu(g_agg@w1l^T + b1l + x@w1r^T)
    agg_kernel<0><<<agg_blocks, 256>>>(x);
    layer_mma<1><<<mma_blocks, 256>>>(x, b1l, nullptr, nullptr, nullptr, N_NODES);

    // Layer 2 + decoder (fused): out_h = agg@w2l^T + b2l + h1@w2r^T;
    //                            out_dx = out_h@wdec^T + bdec
    agg_kernel<1><<<agg_blocks, 256>>>(nullptr);
    layer_mma<2><<<mma_blocks, 256>>>(nullptr, b2l, out_h, bdec, out_dx, N_NODES);
}